// round 15
// baseline (speedup 1.0000x reference)
#include <cuda_runtime.h>
#include <cuda_fp16.h>
#include <math.h>

// ---------------- problem constants ----------------
#define S   8
#define T   12
#define H   256
#define F   316
#define B   1024
#define L   48
#define G   1024      // 4*H
#define KX  320       // padded K for input projection
#define PH  40        // gemm_f16 smem pitch (halves), BK=32
#define PHW 72        // step Ws pitch (halves), BK=64
#define PA  264       // step A-full pitch (halves)
#define NBP 256       // persistent grid size
#define SBH (S * B * H)
#define STEP_SMEM (128 * PA * 2 + 2 * 128 * PHW * 2)   // 104448 B

// ---------------- scratch (device globals; no allocs allowed) ----------------
__device__ __half g_Gin16[96l * B * G];
__device__ __half g_x16[(long)B * 96 * KX];
__device__ __half g_W16ih[(long)S * G * KX];
__device__ __half g_enc16[(long)T * SBH];
__device__ __half g_k2h[(long)T * SBH];
__device__ __half g_h16A[SBH];
__device__ __half g_h16B[SBH];
__device__ __half g_W16e[(long)S * G * H];
__device__ __half g_W16d[(long)S * G * H];
__device__ __half g_M1h[S * H * H];
__device__ float  g_c  [SBH];
__device__ float  g_b12d[S * G];      // b_ih_d + b_hh_d
__device__ float  g_inp[L * B];
__device__ float  g_outs[(long)L * S * B];
__device__ float g_u    [S * H];
__device__ float g_wbqk [S * H];
__device__ float g_wvu  [S * H];
__device__ float g_k2b  [S * H];
__device__ float g_cbqk [S];
__device__ float g_cvu  [S];
__device__ float g_c1   [S];
__device__ float g_bqk  [(long)T * S * B];
__device__ float g_vu   [(long)T * S * B];
__device__ unsigned g_bar_g[2][64];   // gates counters (enc, dec)
__device__ unsigned g_bar_a[64];      // attention counters (dec)

__device__ __forceinline__ float sigf(float x) { return 1.f / (1.f + __expf(-x)); }

__device__ __forceinline__ void mma_f16(float c[4],
    unsigned a0, unsigned a1, unsigned a2, unsigned a3,
    unsigned b0, unsigned b1)
{
    asm volatile(
        "mma.sync.aligned.m16n8k16.row.col.f32.f16.f16.f32 "
        "{%0,%1,%2,%3}, {%4,%5,%6,%7}, {%8,%9}, {%0,%1,%2,%3};"
        : "+f"(c[0]), "+f"(c[1]), "+f"(c[2]), "+f"(c[3])
        : "r"(a0), "r"(a1), "r"(a2), "r"(a3), "r"(b0), "r"(b1));
}

__device__ __forceinline__ void ldsm4(unsigned r[4], unsigned addr) {
    asm volatile("ldmatrix.sync.aligned.m8n8.x4.shared.b16 {%0,%1,%2,%3}, [%4];"
        : "=r"(r[0]), "=r"(r[1]), "=r"(r[2]), "=r"(r[3]) : "r"(addr));
}

__device__ __forceinline__ unsigned sptr(const void* p) {
    return (unsigned)__cvta_generic_to_shared(p);
}
__device__ __forceinline__ void cp16(void* s, const void* g) {
    asm volatile("cp.async.cg.shared.global [%0], [%1], 16;" :: "r"(sptr(s)), "l"(g));
}

// ---- split group barrier primitives ----
// arrive: all block threads' prior mem ops done, then bump counter
__device__ __forceinline__ void ctr_arrive(unsigned* ctr) {
    __syncthreads();
    if (threadIdx.x == 0) {
        __threadfence();
        atomicAdd(ctr, 1u);
    }
}
// wait: spin until counter >= tgt, then acquire
__device__ __forceinline__ void ctr_wait(unsigned* ctr, unsigned tgt) {
    if (threadIdx.x == 0) {
        while (*(volatile unsigned*)ctr < tgt) __nanosleep(32);
        __threadfence();
    }
    __syncthreads();
}

// ---------------- fused prep: h0 seed, inputs, x16, b12, counters ----------
__global__ void prep_fused(const float* __restrict__ x, const float* __restrict__ tgt,
                           const float* __restrict__ b_ih_d, const float* __restrict__ b_hh_d) {
    long i = (long)blockIdx.x * 256 + threadIdx.x;
    if (i < 128) ((unsigned*)g_bar_g)[i] = 0u;
    if (i < 64) g_bar_a[i] = 0u;
    if (i < S * G) g_b12d[i] = b_ih_d[i] + b_hh_d[i];
    if (i < SBH) g_h16A[i] = __float2half(0.f);
    if (i < L * B) {
        int l = (int)(i / B), b = (int)(i % B);
        g_inp[i] = (l == 0) ? x[(long)b * 96 * F + 95 * F + 0]
                            : tgt[(long)b * L + (l - 1)];
    }
    if (i < (long)B * 96 * (KX / 8)) {
        int kq = (int)(i % (KX / 8));
        long br = i / (KX / 8);
        int k = kq * 8;
        const float* xp = x + br * F + k;
        float4 f0 = (k < F) ? *(const float4*)xp : make_float4(0.f, 0.f, 0.f, 0.f);
        float4 f1 = (k + 4 < F) ? *(const float4*)(xp + 4) : make_float4(0.f, 0.f, 0.f, 0.f);
        __half2 h0 = __floats2half2_rn(f0.x, f0.y);
        __half2 h1 = __floats2half2_rn(f0.z, f0.w);
        __half2 h2 = __floats2half2_rn(f1.x, f1.y);
        __half2 h3 = __floats2half2_rn(f1.z, f1.w);
        uint4 u = make_uint4(*(unsigned*)&h0, *(unsigned*)&h1, *(unsigned*)&h2, *(unsigned*)&h3);
        *(uint4*)(g_x16 + br * KX + k) = u;
    }
}

__global__ void conv_wih(const float* __restrict__ Wf) {
    long i = (long)blockIdx.x * 256 + threadIdx.x;
    long tot = (long)S * G * (KX / 8);
    if (i >= tot) return;
    int kq = (int)(i % (KX / 8));
    long sg = i / (KX / 8);
    int k = kq * 8;
    const float* wp = Wf + sg * F + k;
    float4 f0 = *(const float4*)wp;
    float4 f1 = (k + 4 < F) ? *(const float4*)(wp + 4) : make_float4(0.f, 0.f, 0.f, 0.f);
    __half2 h0 = __floats2half2_rn(f0.x, f0.y);
    __half2 h1 = __floats2half2_rn(f0.z, f0.w);
    __half2 h2 = __floats2half2_rn(f1.x, f1.y);
    __half2 h3 = __floats2half2_rn(f1.z, f1.w);
    uint4 u = make_uint4(*(unsigned*)&h0, *(unsigned*)&h1, *(unsigned*)&h2, *(unsigned*)&h3);
    *(uint4*)(g_W16ih + sg * KX + k) = u;
}

// both W_hh conversions in one launch (gate-interleaved, ldmatrix layout)
__global__ void conv_w16_both(const float* __restrict__ We, const float* __restrict__ Wd) {
    const long halfn = (long)S * G * H;
    long i = (long)blockIdx.x * 256 + threadIdx.x;
    const float* W;
    __half* dst;
    long ii = i;
    if (ii >= halfn) { ii -= halfn; W = Wd; dst = g_W16d; }
    else             {              W = We; dst = g_W16e; }
    int k = ii & 255;
    long rr = ii >> 8;
    int r = rr & 127;
    long jj_ = rr >> 7;
    int jb = jj_ & 7;
    int s = (int)(jj_ >> 3);
    int q = (r >> 3) & 3;
    int jloc = (r & 7) + ((r >> 5) << 3);
    dst[ii] = __float2half(W[(long)s * G * H + (q * H + jb * 32 + jloc) * (long)H + k]);
}

// ---------------- warp-parallel precomputes ----------------
__global__ void pc_a(const float* __restrict__ Wout, const float* __restrict__ Wfcout,
                     const float* __restrict__ Win,  const float* __restrict__ b_in) {
    int gw = (blockIdx.x * blockDim.x + threadIdx.x) >> 5;
    int lane = threadIdx.x & 31;
    if (gw >= S * H) return;
    int s = gw >> 8, e = gw & 255;
    const float* wf2 = Wfcout + s * 2 * H + H;
    const float* Wo  = Wout + (long)s * H * H;
    const float* bq = b_in + s * 3 * H;
    const float* bk = bq + H;
    const float* Wq = Win + (long)s * 3 * H * H;
    const float* Wk = Wq + H * H;
    float u = 0.f, wb = 0.f, kb = 0.f;
#pragma unroll
    for (int i = 0; i < 8; i++) {
        int o = lane + i * 32;
        u  += wf2[o] * Wo[o * H + e];
        wb += bq[o]  * Wk[o * H + e];
        kb += Wq[o * H + e] * bk[o];
    }
#pragma unroll
    for (int off = 16; off; off >>= 1) {
        u  += __shfl_xor_sync(0xffffffffu, u, off);
        wb += __shfl_xor_sync(0xffffffffu, wb, off);
        kb += __shfl_xor_sync(0xffffffffu, kb, off);
    }
    if (lane == 0) { g_u[gw] = u; g_wbqk[gw] = wb; g_k2b[gw] = kb; }
}

__global__ void pc_b(const float* __restrict__ Win) {
    int gw = (blockIdx.x * blockDim.x + threadIdx.x) >> 5;
    int lane = threadIdx.x & 31;
    if (gw >= S * H) return;
    int s = gw >> 8, h = gw & 255;
    const float* Wv = Win + (long)s * 3 * H * H + 2 * H * H;
    float wv = 0.f;
#pragma unroll
    for (int i = 0; i < 8; i++) {
        int e = lane + i * 32;
        wv += g_u[s * H + e] * Wv[e * H + h];
    }
#pragma unroll
    for (int off = 16; off; off >>= 1) wv += __shfl_xor_sync(0xffffffffu, wv, off);
    if (lane == 0) g_wvu[gw] = wv;
}

__global__ void pc_c(const float* __restrict__ b_in, const float* __restrict__ Wfcout,
                     const float* __restrict__ b_fcout, const float* __restrict__ b_out) {
    int s = threadIdx.x >> 5;
    int lane = threadIdx.x & 31;
    if (s >= S) return;
    const float* bq = b_in + s * 3 * H;
    const float* bk = bq + H;
    const float* bv = bq + 2 * H;
    const float* wf2 = Wfcout + s * 2 * H + H;
    const float* bo  = b_out + s * H;
    float cvu = 0.f, cb = 0.f, c1 = 0.f;
#pragma unroll
    for (int i = 0; i < 8; i++) {
        int e = lane + i * 32;
        cvu += g_u[s * H + e] * bv[e];
        cb  += bq[e] * bk[e];
        c1  += wf2[e] * bo[e];
    }
#pragma unroll
    for (int off = 16; off; off >>= 1) {
        cvu += __shfl_xor_sync(0xffffffffu, cvu, off);
        cb  += __shfl_xor_sync(0xffffffffu, cb, off);
        c1  += __shfl_xor_sync(0xffffffffu, c1, off);
    }
    if (lane == 0) { g_cvu[s] = cvu; g_cbqk[s] = cb; g_c1[s] = c1 + b_fcout[s]; }
}

__global__ void pc_m1(const float* __restrict__ Win) {
    __shared__ float tq[16][17];
    __shared__ float tk[16][17];
    int s = blockIdx.z;
    const float* Wq = Win + (long)s * 3 * H * H;
    const float* Wk = Wq + H * H;
    int tyy = threadIdx.y, txx = threadIdx.x;
    int hq = blockIdx.y * 16 + tyy;
    int hk = blockIdx.x * 16 + txx;
    float acc = 0.f;
    for (int e0 = 0; e0 < H; e0 += 16) {
        tq[tyy][txx] = Wq[(e0 + tyy) * H + blockIdx.y * 16 + txx];
        tk[tyy][txx] = Wk[(e0 + tyy) * H + hk];
        __syncthreads();
#pragma unroll
        for (int ee = 0; ee < 16; ee++)
            acc = fmaf(tq[ee][tyy], tk[ee][txx], acc);
        __syncthreads();
    }
    g_M1h[(long)s * H * H + hq * H + hk] = __float2half(acc);
}

// ================= generic fp16 tensor-core GEMM (ldmatrix) =================
__global__ void __launch_bounds__(256) gemm_f16(
    const __half* __restrict__ Ag, long sAz, int lda,
    const __half* __restrict__ Wg, long sWz, int ldw,
    const float* __restrict__ b1, const float* __restrict__ b2, long sBz,
    __half* __restrict__ C, long sCz, int ldc,
    int NC, int wdiv)
{
    __shared__ __align__(16) __half As[2][128 * PH];
    __shared__ __align__(16) __half Ws[2][128 * PH];

    const int z  = blockIdx.z;
    const int wi = (z / wdiv) & 7;
    const int m0 = blockIdx.y * 128;
    const int n0 = blockIdx.x * 128;

    const __half* Ap = Ag + (long)z * sAz + (long)m0 * lda;
    const __half* Wp = Wg + (long)wi * sWz + (long)n0 * ldw;

    const int t = threadIdx.x;
    const int w = t >> 5, lane = t & 31;
    const int lq = lane >> 2, lr = lane & 3;
    const int wm = w & 3, wn = w >> 2;

    const unsigned as_b = sptr(&As[0][0]);
    const unsigned ws_b = sptr(&Ws[0][0]);
    const int a_row = wm * 32 + (lane & 15);
    const int a_k8  = (lane >> 4) << 3;
    const unsigned aoff0 = (unsigned)((a_row * PH + a_k8) * 2);
    const unsigned aoff1 = (unsigned)(((a_row + 16) * PH + a_k8) * 2);
    const int b_row = wn * 64 + (lane & 7) + ((lane >> 4) << 3);
    const int b_k8  = ((lane >> 3) & 1) << 3;
    const unsigned boff = (unsigned)((b_row * PH + b_k8) * 2);

    auto issue = [&](int c) {
        int buf = c & 1;
#pragma unroll
        for (int p = 0; p < 2; p++) {
            int idx = t + 256 * p;
            int row = idx >> 2, seg = idx & 3;
            cp16(&As[buf][row * PH + seg * 8], Ap + (long)row * lda + c * 32 + seg * 8);
            cp16(&Ws[buf][row * PH + seg * 8], Wp + (long)row * ldw + c * 32 + seg * 8);
        }
        asm volatile("cp.async.commit_group;");
    };

    float acc[2][8][4];
#pragma unroll
    for (int mt = 0; mt < 2; mt++)
#pragma unroll
        for (int nt = 0; nt < 8; nt++)
#pragma unroll
            for (int v = 0; v < 4; v++) acc[mt][nt][v] = 0.f;

    issue(0);

#pragma unroll 1
    for (int c = 0; c < NC; c++) {
        if (c < NC - 1) {
            issue(c + 1);
            asm volatile("cp.async.wait_group 1;");
        } else {
            asm volatile("cp.async.wait_group 0;");
        }
        __syncthreads();
        int buf = c & 1;
        unsigned ab = as_b + buf * (128 * PH * 2);
        unsigned wbb = ws_b + buf * (128 * PH * 2);
#pragma unroll
        for (int k16 = 0; k16 < 2; k16++) {
            int kb = k16 * 16;
            unsigned a0[4], a1[4];
            ldsm4(a0, ab + aoff0 + kb * 2);
            ldsm4(a1, ab + aoff1 + kb * 2);
#pragma unroll
            for (int bq = 0; bq < 4; bq++) {
                unsigned bb[4];
                ldsm4(bb, wbb + boff + (bq * 16 * PH + kb) * 2);
                mma_f16(acc[0][bq * 2],     a0[0], a0[1], a0[2], a0[3], bb[0], bb[1]);
                mma_f16(acc[1][bq * 2],     a1[0], a1[1], a1[2], a1[3], bb[0], bb[1]);
                mma_f16(acc[0][bq * 2 + 1], a0[0], a0[1], a0[2], a0[3], bb[2], bb[3]);
                mma_f16(acc[1][bq * 2 + 1], a1[0], a1[1], a1[2], a1[3], bb[2], bb[3]);
            }
        }
        __syncthreads();
    }

#pragma unroll
    for (int mt = 0; mt < 2; mt++) {
#pragma unroll
        for (int nt = 0; nt < 8; nt++) {
#pragma unroll
            for (int rh = 0; rh < 2; rh++) {
                int m = m0 + wm * 32 + mt * 16 + lq + rh * 8;
                int n = n0 + wn * 64 + nt * 8 + lr * 2;
                float v0 = acc[mt][nt][rh * 2];
                float v1 = acc[mt][nt][rh * 2 + 1];
                if (b1) { v0 += b1[(long)wi * sBz + n]; v1 += b1[(long)wi * sBz + n + 1]; }
                if (b2) { v0 += b2[(long)wi * sBz + n]; v1 += b2[(long)wi * sBz + n + 1]; }
                *(__half2*)&C[(long)z * sCz + (long)m * ldc + n] = __floats2half2_rn(v0, v1);
            }
        }
    }
}

// ---------------- shared attention device function ----------------
__device__ __forceinline__ void attn_one(const __half* __restrict__ hbase, int sb, int lane,
                                         const float* __restrict__ Wfcout, int lstep)
{
    int ss = sb >> 10;
    const __half2* hp2 = (const __half2*)(hbase + (long)sb * H);
    float2 hf[4];
    {
        __half2 v0 = hp2[lane * 2], v1 = hp2[lane * 2 + 1];
        __half2 v2 = hp2[64 + lane * 2], v3 = hp2[65 + lane * 2];
        hf[0] = __half22float2(v0); hf[1] = __half22float2(v1);
        hf[2] = __half22float2(v2); hf[3] = __half22float2(v3);
    }
    const float* wf = Wfcout + ss * 2 * H;
    float4 w0 = *(const float4*)&wf[lane * 4];
    float4 w1 = *(const float4*)&wf[128 + lane * 4];

    float red[T + 1];
    red[T] = hf[0].x * w0.x + hf[0].y * w0.y + hf[1].x * w0.z + hf[1].y * w0.w
           + hf[2].x * w1.x + hf[2].y * w1.y + hf[3].x * w1.z + hf[3].y * w1.w;
#pragma unroll
    for (int tt = 0; tt < T; tt++) {
        const __half2* kp2 = (const __half2*)(g_k2h + ((long)tt * S * B + sb) * H);
        float2 k0 = __half22float2(kp2[lane * 2]);
        float2 k1 = __half22float2(kp2[lane * 2 + 1]);
        float2 k2_ = __half22float2(kp2[64 + lane * 2]);
        float2 k3 = __half22float2(kp2[65 + lane * 2]);
        red[tt] = hf[0].x * k0.x + hf[0].y * k0.y + hf[1].x * k1.x + hf[1].y * k1.y
                + hf[2].x * k2_.x + hf[2].y * k2_.y + hf[3].x * k3.x + hf[3].y * k3.y;
    }
#pragma unroll
    for (int r = 0; r < T + 1; r++) {
        float v = red[r];
#pragma unroll
        for (int off = 16; off; off >>= 1) v += __shfl_xor_sync(0xffffffffu, v, off);
        red[r] = v;
    }
    float sc[T];
    float mx = -1e30f;
#pragma unroll
    for (int tt = 0; tt < T; tt++) {
        float v = (red[tt] + g_bqk[(long)tt * S * B + sb]) * 0.0625f;
        sc[tt] = v;
        mx = fmaxf(mx, v);
    }
    float sum = 0.f;
#pragma unroll
    for (int tt = 0; tt < T; tt++) { sc[tt] = __expf(sc[tt] - mx); sum += sc[tt]; }
    float inv = 1.f / sum;
    float ctxdot = 0.f;
#pragma unroll
    for (int tt = 0; tt < T; tt++)
        ctxdot = fmaf(sc[tt] * inv, g_vu[(long)tt * S * B + sb], ctxdot);
    if (lane == 0)
        g_outs[(long)lstep * S * B + sb] = red[T] + ctxdot + g_c1[ss];
}

// ====== persistent fp16 step kernel (split counters: attn off crit path) ====
template <int DEC>
__global__ void __launch_bounds__(256, 2) step16_p(
    const __half* __restrict__ h0in,
    __half* __restrict__ hApp, __half* __restrict__ hBpp,
    const __half* __restrict__ W16,
    const float* __restrict__ cvec,
    const __half* __restrict__ gin16,
    __half* __restrict__ enc16,
    const float* __restrict__ Wfcout)
{
    extern __shared__ __align__(16) __half smem[];
    __half* As = smem;
    __half* Ws = smem + 128 * PA;

    const int bid = blockIdx.x;
    const int bx = bid & 3;
    const int m0 = ((bid >> 2) & 7) * 128;
    const int s  = bid >> 5;
    unsigned* gctr = &g_bar_g[DEC][bid >> 2];
    unsigned* actr = &g_bar_a[bid >> 2];

    const int t = threadIdx.x;
    const int w = t >> 5, lane = t & 31;
    const int lq = lane >> 2, lr = lane & 3;
    const int wm = w & 3, wn = w >> 2;

    const unsigned as_b = sptr(As);
    const unsigned ws_b = sptr(Ws);
    const int a_row = wm * 32 + (lane & 15);
    const int a_k8  = (lane >> 4) << 3;
    const unsigned aoff0 = (unsigned)((a_row * PA + a_k8) * 2);
    const unsigned aoff1 = (unsigned)(((a_row + 16) * PA + a_k8) * 2);
    const int b_row = wn * 64 + (lane & 7) + ((lane >> 4) << 3);
    const int b_k8  = ((lane >> 3) & 1) << 3;
    const unsigned boff = (unsigned)((b_row * PHW + b_k8) * 2);

    float creg[32];
    if (DEC) {
#pragma unroll
        for (int hh = 0; hh < 2; hh++)
#pragma unroll
            for (int mt = 0; mt < 2; mt++)
#pragma unroll
                for (int rh = 0; rh < 2; rh++)
#pragma unroll
                    for (int d = 0; d < 2; d++) {
                        int b_row2 = m0 + wm * 32 + mt * 16 + lq + rh * 8;
                        int j = bx * 64 + hh * 32 + (wn * 2 + d) * 8 + lr * 2;
                        float2 cc = *(const float2*)&g_c[((long)s * B + b_row2) * H + j];
                        creg[((hh * 2 + mt) * 2 + rh) * 4 + d * 2]     = cc.x;
                        creg[((hh * 2 + mt) * 2 + rh) * 4 + d * 2 + 1] = cc.y;
                    }
    } else {
#pragma unroll
        for (int i = 0; i < 32; i++) creg[i] = 0.f;
    }

    const int NSTEP = DEC ? (L + 1) : T;

#pragma unroll 1
    for (int it = 0; it < NSTEP; it++) {
        if (it > 0) ctr_wait(gctr, 4u * (unsigned)it);   // h(it-1) ready

        const __half* hin;
        if (DEC) hin = (it == 0) ? h0in : ((it & 1) ? hApp : hBpp);
        else     hin = (it == 0) ? h0in : (enc16 + (long)(it - 1) * SBH);

        if (!DEC || it < L) {
            __half* hout = DEC ? ((it & 1) ? hBpp : hApp) : (enc16 + (long)it * SBH);
            const __half* Aph = hin + ((long)s * B + m0) * H;

            auto issueW = [&](const __half* Wph, int cidx, int buf) {
#pragma unroll
                for (int p = 0; p < 4; p++) {
                    int idx = t + 256 * p;
                    int row = idx >> 3, seg = idx & 7;
                    cp16(&Ws[buf * 128 * PHW + row * PHW + seg * 8],
                         Wph + (long)row * H + cidx * 64 + seg * 8);
                }
            };

            {
#pragma unroll
                for (int p = 0; p < 16; p++) {
                    int idx = t + 256 * p;
                    int row = idx >> 5, seg = idx & 31;
                    cp16(&As[row * PA + seg * 8], Aph + (long)row * H + seg * 8);
                }
                const __half* Wph0 = W16 + ((long)(s * 8 + bx * 2) * 128) * H;
                issueW(Wph0, 0, 0);
                asm volatile("cp.async.commit_group;");
            }

            float accs[2][2][8][4];     // [half][mt][nt][v]
#pragma unroll 1
            for (int hh = 0; hh < 2; hh++) {
                const int jblk = bx * 2 + hh;
                const __half* Wph = W16 + ((long)(s * 8 + jblk) * 128) * H;
                if (hh == 1) {
                    issueW(Wph, 0, 0);
                    asm volatile("cp.async.commit_group;");
                }

#pragma unroll
                for (int mt = 0; mt < 2; mt++)
#pragma unroll
                    for (int nt = 0; nt < 8; nt++)
#pragma unroll
                        for (int v = 0; v < 4; v++) accs[hh][mt][nt][v] = 0.f;

#pragma unroll 1
                for (int c = 0; c < 4; c++) {
                    if (c < 3) {
                        issueW(Wph, c + 1, (c + 1) & 1);
                        asm volatile("cp.async.commit_group;");
                        asm volatile("cp.async.wait_group 1;");
                    } else {
                        asm volatile("cp.async.wait_group 0;");
                    }
                    __syncthreads();
                    int buf = c & 1;
                    unsigned wsbuf = ws_b + buf * (128 * PHW * 2);
#pragma unroll
                    for (int k16 = 0; k16 < 4; k16++) {
                        int ka = c * 64 + k16 * 16;
                        int kb = k16 * 16;
                        unsigned a0[4], a1[4];
                        ldsm4(a0, as_b + aoff0 + ka * 2);
                        ldsm4(a1, as_b + aoff1 + ka * 2);
#pragma unroll
                        for (int bq = 0; bq < 4; bq++) {
                            unsigned bb[4];
                            ldsm4(bb, wsbuf + boff + (bq * 16 * PHW + kb) * 2);
                            mma_f16(accs[hh][0][bq * 2],     a0[0], a0[1], a0[2], a0[3], bb[0], bb[1]);
                            mma_f16(accs[hh][1][bq * 2],     a1[0], a1[1], a1[2], a1[3], bb[0], bb[1]);
                            mma_f16(accs[hh][0][bq * 2 + 1], a0[0], a0[1], a0[2], a0[3], bb[2], bb[3]);
                            mma_f16(accs[hh][1][bq * 2 + 1], a1[0], a1[1], a1[2], a1[3], bb[2], bb[3]);
                        }
                    }
                    __syncthreads();
                }
            }

            // h(it) store overwrites h(it-2)'s buffer: wait for its attn readers
            if (DEC && it >= 2) ctr_wait(actr, 4u * (unsigned)(it - 1));

#pragma unroll
            for (int hh = 0; hh < 2; hh++) {
                const int j0 = bx * 64 + hh * 32;
#pragma unroll
                for (int mt = 0; mt < 2; mt++) {
#pragma unroll
                    for (int rh = 0; rh < 2; rh++) {
                        int b_row2 = m0 + wm * 32 + mt * 16 + lq + rh * 8;
                        float rv = DEC ? g_inp[it * B + b_row2] : 0.f;
#pragma unroll
                        for (int d = 0; d < 2; d++) {
                            int j = j0 + (wn * 2 + d) * 8 + lr * 2;
                            float gate[4][2];
#pragma unroll
                            for (int q = 0; q < 4; q++) {
                                int nt = d * 4 + q;
                                float v0 = accs[hh][mt][nt][rh * 2];
                                float v1 = accs[hh][mt][nt][rh * 2 + 1];
                                int gg = q * H + j;
                                if (DEC) {
                                    float2 x12 = *(const float2*)&g_b12d[s * G + gg];
                                    float2 xc  = *(const float2*)&cvec[s * G + gg];
                                    v0 += x12.x + rv * xc.x;
                                    v1 += x12.y + rv * xc.y;
                                } else {
                                    __half2 xa = *(const __half2*)&gin16[
                                        (((long)(s * T + it)) * B + b_row2) * G + gg];
                                    float2 xf = __half22float2(xa);
                                    v0 += xf.x; v1 += xf.y;
                                }
                                gate[q][0] = v0; gate[q][1] = v1;
                            }
                            int ci = ((hh * 2 + mt) * 2 + rh) * 4 + d * 2;
                            float hn[2];
#pragma unroll
                            for (int dd = 0; dd < 2; dd++) {
                                float c_ = sigf(gate[1][dd]) * creg[ci + dd]
                                         + sigf(gate[0][dd]) * tanhf(gate[2][dd]);
                                creg[ci + dd] = c_;
                                hn[dd] = sigf(gate[3][dd]) * tanhf(c_);
                            }
                            long base = ((long)s * B + b_row2) * H + j;
                            *(__half2*)&hout[base] = __floats2half2_rn(hn[0], hn[1]);
                        }
                    }
                }
            }
            ctr_arrive(gctr);       // h(it) published
        }

        // attention for step it-1 (group-local rows); overlaps peers' next GEMM
        if (DEC && it >= 1) {
#pragma unroll 1
            for (int rep = 0; rep < 4; rep++) {
                int sb = s * B + m0 + bx * 32 + w + rep * 8;
                attn_one(hin, sb, lane, Wfcout, it - 1);
            }
            ctr_arrive(actr);       // h(it-1) attn reads done
        }
    }

    if (!DEC) {
#pragma unroll
        for (int hh = 0; hh < 2; hh++)
#pragma unroll
            for (int mt = 0; mt < 2; mt++)
#pragma unroll
                for (int rh = 0; rh < 2; rh++)
#pragma unroll
                    for (int d = 0; d < 2; d++) {
                        int b_row2 = m0 + wm * 32 + mt * 16 + lq + rh * 8;
                        int j = bx * 64 + hh * 32 + (wn * 2 + d) * 8 + lr * 2;
                        int ci = ((hh * 2 + mt) * 2 + rh) * 4 + d * 2;
                        *(float2*)&g_c[((long)s * B + b_row2) * H + j] =
                            make_float2(creg[ci], creg[ci + 1]);
                    }
    }
}

// ---------------- per-(t,s,b) scalars ----------------
__global__ void pc_scal_kernel() {
    int gtid = blockIdx.x * blockDim.x + threadIdx.x;
    int warp = gtid >> 5;
    int lane = threadIdx.x & 31;
    if (warp >= T * S * B) return;
    int s = (warp >> 10) & 7;

    const __half2* ep = (const __half2*)(g_enc16 + (long)warp * H);
    const float* wb = g_wbqk + s * H;
    const float* wv = g_wvu + s * H;
    float db = 0.f, dv = 0.f;
#pragma unroll
    for (int u = 0; u < 2; u++) {
        int e = lane * 4 + u * 128;
        float2 e0 = __half22float2(ep[lane * 2 + u * 64]);
        float2 e1 = __half22float2(ep[lane * 2 + 1 + u * 64]);
        float4 b4 = *(const float4*)&wb[e];
        float4 v4 = *(const float4*)&wv[e];
        db += e0.x * b4.x + e0.y * b4.y + e1.x * b4.z + e1.y * b4.w;
        dv += e0.x * v4.x + e0.y * v4.y + e1.x * v4.z + e1.y * v4.w;
    }
#pragma unroll
    for (int off = 16; off; off >>= 1) {
        db += __shfl_xor_sync(0xffffffffu, db, off);
        dv += __shfl_xor_sync(0xffffffffu, dv, off);
    }
    if (lane == 0) {
        g_bqk[warp] = db + g_cbqk[s];
        g_vu[warp]  = dv + g_cvu[s];
    }
}

// ---------------- final 8->1 mix ----------------
__global__ void final_kernel(const float* __restrict__ Wfc, const float* __restrict__ bfc,
                             float* __restrict__ out) {
    int i = blockIdx.x * blockDim.x + threadIdx.x;
    if (i >= B * L) return;
    int b = i / L, l = i % L;
    float acc = bfc[0];
#pragma unroll
    for (int s = 0; s < S; s++)
        acc += g_outs[(long)l * S * B + (long)s * B + b] * Wfc[s];
    out[i] = acc;
}

// ---------------- host launch ----------------
extern "C" void kernel_launch(void* const* d_in, const int* in_sizes, int n_in,
                              void* d_out, int out_size) {
    const float* x       = (const float*)d_in[0];
    const float* tgt     = (const float*)d_in[1];
    const float* W_ih_e  = (const float*)d_in[2];
    const float* W_hh_e  = (const float*)d_in[3];
    const float* b_ih_e  = (const float*)d_in[4];
    const float* b_hh_e  = (const float*)d_in[5];
    const float* W_ih_d  = (const float*)d_in[6];
    const float* W_hh_d  = (const float*)d_in[7];
    const float* b_ih_d  = (const float*)d_in[8];
    const float* b_hh_d  = (const float*)d_in[9];
    const float* W_in    = (const float*)d_in[10];
    const float* b_in    = (const float*)d_in[11];
    const float* W_out   = (const float*)d_in[12];
    const float* b_out   = (const float*)d_in[13];
    const float* W_fcout = (const float*)d_in[14];
    const float* b_fcout = (const float*)d_in[15];
    const float* W_fc    = (const float*)d_in[16];
    const float* b_fc    = (const float*)d_in[17];
    float* out = (float*)d_out;

    __half *gin16, *x16, *w16ih, *enc16, *k2h, *hA, *hB, *W16e, *W16d, *M1h;
    float *k2b;
    cudaGetSymbolAddress((void**)&gin16, g_Gin16);
    cudaGetSymbolAddress((void**)&x16,   g_x16);
    cudaGetSymbolAddress((void**)&w16ih, g_W16ih);
    cudaGetSymbolAddress((void**)&enc16, g_enc16);
    cudaGetSymbolAddress((void**)&k2h,   g_k2h);
    cudaGetSymbolAddress((void**)&hA,    g_h16A);
    cudaGetSymbolAddress((void**)&hB,    g_h16B);
    cudaGetSymbolAddress((void**)&W16e,  g_W16e);
    cudaGetSymbolAddress((void**)&W16d,  g_W16d);
    cudaGetSymbolAddress((void**)&M1h,   g_M1h);
    cudaGetSymbolAddress((void**)&k2b,   g_k2b);

    static int smem_set = 0;
    if (!smem_set) {
        cudaFuncSetAttribute(step16_p<0>, cudaFuncAttributeMaxDynamicSharedMemorySize, STEP_SMEM);
        cudaFuncSetAttribute(step16_p<1>, cudaFuncAttributeMaxDynamicSharedMemorySize, STEP_SMEM);
        smem_set = 1;
    }

    prep_fused<<<(int)(((long)B * 96 * (KX / 8) + 255) / 256), 256>>>(x, tgt, b_ih_d, b_hh_d);
    conv_wih<<<(int)(((long)S * G * (KX / 8) + 255) / 256), 256>>>(W_ih_e);
    conv_w16_both<<<(int)(2 * ((long)S * G * H) / 256), 256>>>(W_hh_e, W_hh_d);
    pc_a<<<S * H * 32 / 256, 256>>>(W_out, W_fcout, W_in, b_in);
    pc_b<<<S * H * 32 / 256, 256>>>(W_in);
    pc_c<<<1, 256>>>(b_in, W_fcout, b_fcout, b_out);
    pc_m1<<<dim3(16, 16, 8), dim3(16, 16)>>>(W_in);

    gemm_f16<<<dim3(G / 128, B / 128, 96), 256>>>(
        x16, (long)KX, 96 * KX,
        w16ih, (long)G * KX, KX,
        b_ih_e, b_hh_e, G,
        gin16, (long)B * G, G, KX / 32, 12);

    step16_p<0><<<NBP, 256, STEP_SMEM>>>(
        hA, nullptr, nullptr, W16e,
        nullptr, gin16, enc16, nullptr);

    pc_scal_kernel<<<(T * S * B * 32 + 255) / 256, 256>>>();
    gemm_f16<<<dim3(H / 128, B / 128, T * S), 256>>>(
        enc16, (long)B * H, H,
        M1h, (long)H * H, H,
        k2b, nullptr, H,
        k2h, (long)B * H, H, H / 32, 1);

    step16_p<1><<<NBP, 256, STEP_SMEM>>>(
        enc16 + (long)11 * SBH, hA, hB, W16d,
        W_ih_d, nullptr, nullptr, W_fcout);

    final_kernel<<<(B * L + 255) / 256, 256>>>(W_fc, b_fc, out);
}

// round 17
// speedup vs baseline: 1.4917x; 1.4917x over previous
#include <cuda_runtime.h>
#include <cuda_fp16.h>
#include <math.h>

// ---------------- problem constants ----------------
#define S   8
#define T   12
#define H   256
#define F   316
#define B   1024
#define L   48
#define G   1024      // 4*H
#define KX  320       // padded K for input projection
#define PH  40        // gemm_f16 smem pitch (halves), BK=32
#define PHW 72        // step Ws pitch (halves), BK=64
#define PA  264       // step A-full pitch (halves)
#define NBP 256       // persistent grid size
#define SBH (S * B * H)
#define STEP_SMEM (128 * PA * 2 + 2 * 128 * PHW * 2)   // 104448 B

// ---------------- scratch (device globals; no allocs allowed) ----------------
__device__ __half g_Gin16[96l * B * G];
__device__ __half g_x16[(long)B * 96 * KX];
__device__ __half g_W16ih[(long)S * G * KX];
__device__ __half g_enc16[(long)T * SBH];
__device__ __half g_k2h[(long)T * SBH];
__device__ __half g_h16A[SBH];
__device__ __half g_h16B[SBH];
__device__ __half g_W16e[(long)S * G * H];
__device__ __half g_W16d[(long)S * G * H];
__device__ __half g_M1h[S * H * H];
__device__ float  g_c  [SBH];
__device__ float  g_b12d[S * G];      // b_ih_d + b_hh_d
__device__ float  g_inp[L * B];
__device__ float  g_outs[(long)L * S * B];
__device__ float g_u    [S * H];
__device__ float g_wbqk [S * H];
__device__ float g_wvu  [S * H];
__device__ float g_k2b  [S * H];
__device__ float g_cbqk [S];
__device__ float g_cvu  [S];
__device__ float g_c1   [S];
__device__ float g_bqk  [(long)T * S * B];
__device__ float g_vu   [(long)T * S * B];
__device__ unsigned g_gbarr[2][64];   // per-group step counters (enc, dec)

__device__ __forceinline__ float sigf(float x) { return 1.f / (1.f + __expf(-x)); }

__device__ __forceinline__ void mma_f16(float c[4],
    unsigned a0, unsigned a1, unsigned a2, unsigned a3,
    unsigned b0, unsigned b1)
{
    asm volatile(
        "mma.sync.aligned.m16n8k16.row.col.f32.f16.f16.f32 "
        "{%0,%1,%2,%3}, {%4,%5,%6,%7}, {%8,%9}, {%0,%1,%2,%3};"
        : "+f"(c[0]), "+f"(c[1]), "+f"(c[2]), "+f"(c[3])
        : "r"(a0), "r"(a1), "r"(a2), "r"(a3), "r"(b0), "r"(b1));
}

__device__ __forceinline__ void ldsm4(unsigned r[4], unsigned addr) {
    asm volatile("ldmatrix.sync.aligned.m8n8.x4.shared.b16 {%0,%1,%2,%3}, [%4];"
        : "=r"(r[0]), "=r"(r[1]), "=r"(r[2]), "=r"(r[3]) : "r"(addr));
}

__device__ __forceinline__ unsigned sptr(const void* p) {
    return (unsigned)__cvta_generic_to_shared(p);
}
__device__ __forceinline__ void cp16(void* s, const void* g) {
    asm volatile("cp.async.cg.shared.global [%0], [%1], 16;" :: "r"(sptr(s)), "l"(g));
}

// group barrier: 4 blocks of one (s,m0) group sync on a counter
__device__ __forceinline__ void group_bar(unsigned* ctr, int it) {
    __syncthreads();
    if (threadIdx.x == 0) {
        __threadfence();
        atomicAdd(ctr, 1u);
        unsigned tgt = 4u * (unsigned)(it + 1);
        while (*(volatile unsigned*)ctr < tgt) __nanosleep(32);
        __threadfence();
    }
    __syncthreads();
}

// ---------------- fused prep: h0 seed, inputs, x16, b12, counters ----------
__global__ void prep_fused(const float* __restrict__ x, const float* __restrict__ tgt,
                           const float* __restrict__ b_ih_d, const float* __restrict__ b_hh_d) {
    long i = (long)blockIdx.x * 256 + threadIdx.x;
    if (i < 128) ((unsigned*)g_gbarr)[i] = 0u;
    if (i < S * G) g_b12d[i] = b_ih_d[i] + b_hh_d[i];
    if (i < SBH) g_h16A[i] = __float2half(0.f);
    if (i < L * B) {
        int l = (int)(i / B), b = (int)(i % B);
        g_inp[i] = (l == 0) ? x[(long)b * 96 * F + 95 * F + 0]
                            : tgt[(long)b * L + (l - 1)];
    }
    if (i < (long)B * 96 * (KX / 8)) {
        int kq = (int)(i % (KX / 8));
        long br = i / (KX / 8);
        int k = kq * 8;
        const float* xp = x + br * F + k;
        float4 f0 = (k < F) ? *(const float4*)xp : make_float4(0.f, 0.f, 0.f, 0.f);
        float4 f1 = (k + 4 < F) ? *(const float4*)(xp + 4) : make_float4(0.f, 0.f, 0.f, 0.f);
        __half2 h0 = __floats2half2_rn(f0.x, f0.y);
        __half2 h1 = __floats2half2_rn(f0.z, f0.w);
        __half2 h2 = __floats2half2_rn(f1.x, f1.y);
        __half2 h3 = __floats2half2_rn(f1.z, f1.w);
        uint4 u = make_uint4(*(unsigned*)&h0, *(unsigned*)&h1, *(unsigned*)&h2, *(unsigned*)&h3);
        *(uint4*)(g_x16 + br * KX + k) = u;
    }
}

__global__ void conv_wih(const float* __restrict__ Wf) {
    long i = (long)blockIdx.x * 256 + threadIdx.x;
    long tot = (long)S * G * (KX / 8);
    if (i >= tot) return;
    int kq = (int)(i % (KX / 8));
    long sg = i / (KX / 8);
    int k = kq * 8;
    const float* wp = Wf + sg * F + k;
    float4 f0 = *(const float4*)wp;
    float4 f1 = (k + 4 < F) ? *(const float4*)(wp + 4) : make_float4(0.f, 0.f, 0.f, 0.f);
    __half2 h0 = __floats2half2_rn(f0.x, f0.y);
    __half2 h1 = __floats2half2_rn(f0.z, f0.w);
    __half2 h2 = __floats2half2_rn(f1.x, f1.y);
    __half2 h3 = __floats2half2_rn(f1.z, f1.w);
    uint4 u = make_uint4(*(unsigned*)&h0, *(unsigned*)&h1, *(unsigned*)&h2, *(unsigned*)&h3);
    *(uint4*)(g_W16ih + sg * KX + k) = u;
}

// both W_hh conversions in one launch (gate-interleaved, ldmatrix layout)
__global__ void conv_w16_both(const float* __restrict__ We, const float* __restrict__ Wd) {
    const long halfn = (long)S * G * H;
    long i = (long)blockIdx.x * 256 + threadIdx.x;
    const float* W;
    __half* dst;
    long ii = i;
    if (ii >= halfn) { ii -= halfn; W = Wd; dst = g_W16d; }
    else             {              W = We; dst = g_W16e; }
    int k = ii & 255;
    long rr = ii >> 8;
    int r = rr & 127;
    long jj_ = rr >> 7;
    int jb = jj_ & 7;
    int s = (int)(jj_ >> 3);
    int q = (r >> 3) & 3;
    int jloc = (r & 7) + ((r >> 5) << 3);
    dst[ii] = __float2half(W[(long)s * G * H + (q * H + jb * 32 + jloc) * (long)H + k]);
}

// ---------------- warp-parallel precomputes ----------------
__global__ void pc_a(const float* __restrict__ Wout, const float* __restrict__ Wfcout,
                     const float* __restrict__ Win,  const float* __restrict__ b_in) {
    int gw = (blockIdx.x * blockDim.x + threadIdx.x) >> 5;
    int lane = threadIdx.x & 31;
    if (gw >= S * H) return;
    int s = gw >> 8, e = gw & 255;
    const float* wf2 = Wfcout + s * 2 * H + H;
    const float* Wo  = Wout + (long)s * H * H;
    const float* bq = b_in + s * 3 * H;
    const float* bk = bq + H;
    const float* Wq = Win + (long)s * 3 * H * H;
    const float* Wk = Wq + H * H;
    float u = 0.f, wb = 0.f, kb = 0.f;
#pragma unroll
    for (int i = 0; i < 8; i++) {
        int o = lane + i * 32;
        u  += wf2[o] * Wo[o * H + e];
        wb += bq[o]  * Wk[o * H + e];
        kb += Wq[o * H + e] * bk[o];
    }
#pragma unroll
    for (int off = 16; off; off >>= 1) {
        u  += __shfl_xor_sync(0xffffffffu, u, off);
        wb += __shfl_xor_sync(0xffffffffu, wb, off);
        kb += __shfl_xor_sync(0xffffffffu, kb, off);
    }
    if (lane == 0) { g_u[gw] = u; g_wbqk[gw] = wb; g_k2b[gw] = kb; }
}

__global__ void pc_b(const float* __restrict__ Win) {
    int gw = (blockIdx.x * blockDim.x + threadIdx.x) >> 5;
    int lane = threadIdx.x & 31;
    if (gw >= S * H) return;
    int s = gw >> 8, h = gw & 255;
    const float* Wv = Win + (long)s * 3 * H * H + 2 * H * H;
    float wv = 0.f;
#pragma unroll
    for (int i = 0; i < 8; i++) {
        int e = lane + i * 32;
        wv += g_u[s * H + e] * Wv[e * H + h];
    }
#pragma unroll
    for (int off = 16; off; off >>= 1) wv += __shfl_xor_sync(0xffffffffu, wv, off);
    if (lane == 0) g_wvu[gw] = wv;
}

__global__ void pc_c(const float* __restrict__ b_in, const float* __restrict__ Wfcout,
                     const float* __restrict__ b_fcout, const float* __restrict__ b_out) {
    int s = threadIdx.x >> 5;
    int lane = threadIdx.x & 31;
    if (s >= S) return;
    const float* bq = b_in + s * 3 * H;
    const float* bk = bq + H;
    const float* bv = bq + 2 * H;
    const float* wf2 = Wfcout + s * 2 * H + H;
    const float* bo  = b_out + s * H;
    float cvu = 0.f, cb = 0.f, c1 = 0.f;
#pragma unroll
    for (int i = 0; i < 8; i++) {
        int e = lane + i * 32;
        cvu += g_u[s * H + e] * bv[e];
        cb  += bq[e] * bk[e];
        c1  += wf2[e] * bo[e];
    }
#pragma unroll
    for (int off = 16; off; off >>= 1) {
        cvu += __shfl_xor_sync(0xffffffffu, cvu, off);
        cb  += __shfl_xor_sync(0xffffffffu, cb, off);
        c1  += __shfl_xor_sync(0xffffffffu, c1, off);
    }
    if (lane == 0) { g_cvu[s] = cvu; g_cbqk[s] = cb; g_c1[s] = c1 + b_fcout[s]; }
}

__global__ void pc_m1(const float* __restrict__ Win) {
    __shared__ float tq[16][17];
    __shared__ float tk[16][17];
    int s = blockIdx.z;
    const float* Wq = Win + (long)s * 3 * H * H;
    const float* Wk = Wq + H * H;
    int tyy = threadIdx.y, txx = threadIdx.x;
    int hq = blockIdx.y * 16 + tyy;
    int hk = blockIdx.x * 16 + txx;
    float acc = 0.f;
    for (int e0 = 0; e0 < H; e0 += 16) {
        tq[tyy][txx] = Wq[(e0 + tyy) * H + blockIdx.y * 16 + txx];
        tk[tyy][txx] = Wk[(e0 + tyy) * H + hk];
        __syncthreads();
#pragma unroll
        for (int ee = 0; ee < 16; ee++)
            acc = fmaf(tq[ee][tyy], tk[ee][txx], acc);
        __syncthreads();
    }
    g_M1h[(long)s * H * H + hq * H + hk] = __float2half(acc);
}

// ================= generic fp16 tensor-core GEMM (ldmatrix) =================
__global__ void __launch_bounds__(256) gemm_f16(
    const __half* __restrict__ Ag, long sAz, int lda,
    const __half* __restrict__ Wg, long sWz, int ldw,
    const float* __restrict__ b1, const float* __restrict__ b2, long sBz,
    __half* __restrict__ C, long sCz, int ldc,
    int NC, int wdiv)
{
    __shared__ __align__(16) __half As[2][128 * PH];
    __shared__ __align__(16) __half Ws[2][128 * PH];

    const int z  = blockIdx.z;
    const int wi = (z / wdiv) & 7;
    const int m0 = blockIdx.y * 128;
    const int n0 = blockIdx.x * 128;

    const __half* Ap = Ag + (long)z * sAz + (long)m0 * lda;
    const __half* Wp = Wg + (long)wi * sWz + (long)n0 * ldw;

    const int t = threadIdx.x;
    const int w = t >> 5, lane = t & 31;
    const int lq = lane >> 2, lr = lane & 3;
    const int wm = w & 3, wn = w >> 2;

    const unsigned as_b = sptr(&As[0][0]);
    const unsigned ws_b = sptr(&Ws[0][0]);
    const int a_row = wm * 32 + (lane & 15);
    const int a_k8  = (lane >> 4) << 3;
    const unsigned aoff0 = (unsigned)((a_row * PH + a_k8) * 2);
    const unsigned aoff1 = (unsigned)(((a_row + 16) * PH + a_k8) * 2);
    const int b_row = wn * 64 + (lane & 7) + ((lane >> 4) << 3);
    const int b_k8  = ((lane >> 3) & 1) << 3;
    const unsigned boff = (unsigned)((b_row * PH + b_k8) * 2);

    auto issue = [&](int c) {
        int buf = c & 1;
#pragma unroll
        for (int p = 0; p < 2; p++) {
            int idx = t + 256 * p;
            int row = idx >> 2, seg = idx & 3;
            cp16(&As[buf][row * PH + seg * 8], Ap + (long)row * lda + c * 32 + seg * 8);
            cp16(&Ws[buf][row * PH + seg * 8], Wp + (long)row * ldw + c * 32 + seg * 8);
        }
        asm volatile("cp.async.commit_group;");
    };

    float acc[2][8][4];
#pragma unroll
    for (int mt = 0; mt < 2; mt++)
#pragma unroll
        for (int nt = 0; nt < 8; nt++)
#pragma unroll
            for (int v = 0; v < 4; v++) acc[mt][nt][v] = 0.f;

    issue(0);

#pragma unroll 1
    for (int c = 0; c < NC; c++) {
        if (c < NC - 1) {
            issue(c + 1);
            asm volatile("cp.async.wait_group 1;");
        } else {
            asm volatile("cp.async.wait_group 0;");
        }
        __syncthreads();
        int buf = c & 1;
        unsigned ab = as_b + buf * (128 * PH * 2);
        unsigned wbb = ws_b + buf * (128 * PH * 2);
#pragma unroll
        for (int k16 = 0; k16 < 2; k16++) {
            int kb = k16 * 16;
            unsigned a0[4], a1[4];
            ldsm4(a0, ab + aoff0 + kb * 2);
            ldsm4(a1, ab + aoff1 + kb * 2);
#pragma unroll
            for (int bq = 0; bq < 4; bq++) {
                unsigned bb[4];
                ldsm4(bb, wbb + boff + (bq * 16 * PH + kb) * 2);
                mma_f16(acc[0][bq * 2],     a0[0], a0[1], a0[2], a0[3], bb[0], bb[1]);
                mma_f16(acc[1][bq * 2],     a1[0], a1[1], a1[2], a1[3], bb[0], bb[1]);
                mma_f16(acc[0][bq * 2 + 1], a0[0], a0[1], a0[2], a0[3], bb[2], bb[3]);
                mma_f16(acc[1][bq * 2 + 1], a1[0], a1[1], a1[2], a1[3], bb[2], bb[3]);
            }
        }
        __syncthreads();
    }

#pragma unroll
    for (int mt = 0; mt < 2; mt++) {
#pragma unroll
        for (int nt = 0; nt < 8; nt++) {
#pragma unroll
            for (int rh = 0; rh < 2; rh++) {
                int m = m0 + wm * 32 + mt * 16 + lq + rh * 8;
                int n = n0 + wn * 64 + nt * 8 + lr * 2;
                float v0 = acc[mt][nt][rh * 2];
                float v1 = acc[mt][nt][rh * 2 + 1];
                if (b1) { v0 += b1[(long)wi * sBz + n]; v1 += b1[(long)wi * sBz + n + 1]; }
                if (b2) { v0 += b2[(long)wi * sBz + n]; v1 += b2[(long)wi * sBz + n + 1]; }
                *(__half2*)&C[(long)z * sCz + (long)m * ldc + n] = __floats2half2_rn(v0, v1);
            }
        }
    }
}

// ---------------- shared attention device function ----------------
__device__ __forceinline__ void attn_one(const __half* __restrict__ hbase, int sb, int lane,
                                         const float* __restrict__ Wfcout, int lstep)
{
    int ss = sb >> 10;
    const __half2* hp2 = (const __half2*)(hbase + (long)sb * H);
    float2 hf[4];
    {
        __half2 v0 = hp2[lane * 2], v1 = hp2[lane * 2 + 1];
        __half2 v2 = hp2[64 + lane * 2], v3 = hp2[65 + lane * 2];
        hf[0] = __half22float2(v0); hf[1] = __half22float2(v1);
        hf[2] = __half22float2(v2); hf[3] = __half22float2(v3);
    }
    const float* wf = Wfcout + ss * 2 * H;
    float4 w0 = *(const float4*)&wf[lane * 4];
    float4 w1 = *(const float4*)&wf[128 + lane * 4];

    float red[T + 1];
    red[T] = hf[0].x * w0.x + hf[0].y * w0.y + hf[1].x * w0.z + hf[1].y * w0.w
           + hf[2].x * w1.x + hf[2].y * w1.y + hf[3].x * w1.z + hf[3].y * w1.w;
#pragma unroll
    for (int tt = 0; tt < T; tt++) {
        const __half2* kp2 = (const __half2*)(g_k2h + ((long)tt * S * B + sb) * H);
        float2 k0 = __half22float2(kp2[lane * 2]);
        float2 k1 = __half22float2(kp2[lane * 2 + 1]);
        float2 k2_ = __half22float2(kp2[64 + lane * 2]);
        float2 k3 = __half22float2(kp2[65 + lane * 2]);
        red[tt] = hf[0].x * k0.x + hf[0].y * k0.y + hf[1].x * k1.x + hf[1].y * k1.y
                + hf[2].x * k2_.x + hf[2].y * k2_.y + hf[3].x * k3.x + hf[3].y * k3.y;
    }
#pragma unroll
    for (int r = 0; r < T + 1; r++) {
        float v = red[r];
#pragma unroll
        for (int off = 16; off; off >>= 1) v += __shfl_xor_sync(0xffffffffu, v, off);
        red[r] = v;
    }
    float sc[T];
    float mx = -1e30f;
#pragma unroll
    for (int tt = 0; tt < T; tt++) {
        float v = (red[tt] + g_bqk[(long)tt * S * B + sb]) * 0.0625f;
        sc[tt] = v;
        mx = fmaxf(mx, v);
    }
    float sum = 0.f;
#pragma unroll
    for (int tt = 0; tt < T; tt++) { sc[tt] = __expf(sc[tt] - mx); sum += sc[tt]; }
    float inv = 1.f / sum;
    float ctxdot = 0.f;
#pragma unroll
    for (int tt = 0; tt < T; tt++)
        ctxdot = fmaf(sc[tt] * inv, g_vu[(long)tt * S * B + sb], ctxdot);
    if (lane == 0)
        g_outs[(long)lstep * S * B + sb] = red[T] + ctxdot + g_c1[ss];
}

// ============ persistent fp16 step kernel (group-local barriers) ============
template <int DEC>
__global__ void __launch_bounds__(256, 2) step16_p(
    const __half* __restrict__ h0in,
    __half* __restrict__ hApp, __half* __restrict__ hBpp,
    const __half* __restrict__ W16,
    const float* __restrict__ b12,
    const float* __restrict__ cvec,
    const __half* __restrict__ gin16,
    __half* __restrict__ enc16,
    const float* __restrict__ Wfcout)
{
    extern __shared__ __align__(16) __half smem[];
    __half* As = smem;
    __half* Ws = smem + 128 * PA;

    const int bid = blockIdx.x;
    const int bx = bid & 3;
    const int m0 = ((bid >> 2) & 7) * 128;
    const int s  = bid >> 5;
    unsigned* gctr = &g_gbarr[DEC][bid >> 2];

    const int t = threadIdx.x;
    const int w = t >> 5, lane = t & 31;
    const int lq = lane >> 2, lr = lane & 3;
    const int wm = w & 3, wn = w >> 2;

    const unsigned as_b = sptr(As);
    const unsigned ws_b = sptr(Ws);
    const int a_row = wm * 32 + (lane & 15);
    const int a_k8  = (lane >> 4) << 3;
    const unsigned aoff0 = (unsigned)((a_row * PA + a_k8) * 2);
    const unsigned aoff1 = (unsigned)(((a_row + 16) * PA + a_k8) * 2);
    const int b_row = wn * 64 + (lane & 7) + ((lane >> 4) << 3);
    const int b_k8  = ((lane >> 3) & 1) << 3;
    const unsigned boff = (unsigned)((b_row * PHW + b_k8) * 2);

    float creg[32];
    if (DEC) {
#pragma unroll
        for (int hh = 0; hh < 2; hh++)
#pragma unroll
            for (int mt = 0; mt < 2; mt++)
#pragma unroll
                for (int rh = 0; rh < 2; rh++)
#pragma unroll
                    for (int d = 0; d < 2; d++) {
                        int b_row2 = m0 + wm * 32 + mt * 16 + lq + rh * 8;
                        int j = bx * 64 + hh * 32 + (wn * 2 + d) * 8 + lr * 2;
                        float2 cc = *(const float2*)&g_c[((long)s * B + b_row2) * H + j];
                        creg[((hh * 2 + mt) * 2 + rh) * 4 + d * 2]     = cc.x;
                        creg[((hh * 2 + mt) * 2 + rh) * 4 + d * 2 + 1] = cc.y;
                    }
    } else {
#pragma unroll
        for (int i = 0; i < 32; i++) creg[i] = 0.f;
    }

    const int NSTEP = DEC ? (L + 1) : T;

#pragma unroll 1
    for (int it = 0; it < NSTEP; it++) {
        const __half* hin;
        if (DEC) hin = (it == 0) ? h0in : ((it & 1) ? hApp : hBpp);
        else     hin = (it == 0) ? h0in : (enc16 + (long)(it - 1) * SBH);

        if (!DEC || it < L) {
            __half* hout = DEC ? ((it & 1) ? hBpp : hApp) : (enc16 + (long)it * SBH);
            const __half* Aph = hin + ((long)s * B + m0) * H;

            auto issueW = [&](const __half* Wph, int cidx, int buf) {
#pragma unroll
                for (int p = 0; p < 4; p++) {
                    int idx = t + 256 * p;
                    int row = idx >> 3, seg = idx & 7;
                    cp16(&Ws[buf * 128 * PHW + row * PHW + seg * 8],
                         Wph + (long)row * H + cidx * 64 + seg * 8);
                }
            };

            {
#pragma unroll
                for (int p = 0; p < 16; p++) {
                    int idx = t + 256 * p;
                    int row = idx >> 5, seg = idx & 31;
                    cp16(&As[row * PA + seg * 8], Aph + (long)row * H + seg * 8);
                }
                const __half* Wph0 = W16 + ((long)(s * 8 + bx * 2) * 128) * H;
                issueW(Wph0, 0, 0);
                asm volatile("cp.async.commit_group;");
            }

#pragma unroll 1
            for (int hh = 0; hh < 2; hh++) {
                const int jblk = bx * 2 + hh;
                const __half* Wph = W16 + ((long)(s * 8 + jblk) * 128) * H;
                if (hh == 1) {
                    issueW(Wph, 0, 0);
                    asm volatile("cp.async.commit_group;");
                }

                float acc[2][8][4];
#pragma unroll
                for (int mt = 0; mt < 2; mt++)
#pragma unroll
                    for (int nt = 0; nt < 8; nt++)
#pragma unroll
                        for (int v = 0; v < 4; v++) acc[mt][nt][v] = 0.f;

#pragma unroll 1
                for (int c = 0; c < 4; c++) {
                    if (c < 3) {
                        issueW(Wph, c + 1, (c + 1) & 1);
                        asm volatile("cp.async.commit_group;");
                        asm volatile("cp.async.wait_group 1;");
                    } else {
                        asm volatile("cp.async.wait_group 0;");
                    }
                    __syncthreads();
                    int buf = c & 1;
                    unsigned wsbuf = ws_b + buf * (128 * PHW * 2);
#pragma unroll
                    for (int k16 = 0; k16 < 4; k16++) {
                        int ka = c * 64 + k16 * 16;
                        int kb = k16 * 16;
                        unsigned a0[4], a1[4];
                        ldsm4(a0, as_b + aoff0 + ka * 2);
                        ldsm4(a1, as_b + aoff1 + ka * 2);
#pragma unroll
                        for (int bq = 0; bq < 4; bq++) {
                            unsigned bb[4];
                            ldsm4(bb, wsbuf + boff + (bq * 16 * PHW + kb) * 2);
                            mma_f16(acc[0][bq * 2],     a0[0], a0[1], a0[2], a0[3], bb[0], bb[1]);
                            mma_f16(acc[1][bq * 2],     a1[0], a1[1], a1[2], a1[3], bb[0], bb[1]);
                            mma_f16(acc[0][bq * 2 + 1], a0[0], a0[1], a0[2], a0[3], bb[2], bb[3]);
                            mma_f16(acc[1][bq * 2 + 1], a1[0], a1[1], a1[2], a1[3], bb[2], bb[3]);
                        }
                    }
                    __syncthreads();
                }

                const int j0 = bx * 64 + hh * 32;
#pragma unroll
                for (int mt = 0; mt < 2; mt++) {
#pragma unroll
                    for (int rh = 0; rh < 2; rh++) {
                        int b_row2 = m0 + wm * 32 + mt * 16 + lq + rh * 8;
                        float rv = DEC ? g_inp[it * B + b_row2] : 0.f;
#pragma unroll
                        for (int d = 0; d < 2; d++) {
                            int j = j0 + (wn * 2 + d) * 8 + lr * 2;
                            float gate[4][2];
#pragma unroll
                            for (int q = 0; q < 4; q++) {
                                int nt = d * 4 + q;
                                float v0 = acc[mt][nt][rh * 2];
                                float v1 = acc[mt][nt][rh * 2 + 1];
                                int gg = q * H + j;
                                if (DEC) {
                                    float2 x12 = *(const float2*)&b12[s * G + gg];
                                    float2 xc  = *(const float2*)&cvec[s * G + gg];
                                    v0 += x12.x + rv * xc.x;
                                    v1 += x12.y + rv * xc.y;
                                } else {
                                    __half2 xa = *(const __half2*)&gin16[
                                        (((long)(s * T + it)) * B + b_row2) * G + gg];
                                    float2 xf = __half22float2(xa);
                                    v0 += xf.x; v1 += xf.y;
                                }
                                gate[q][0] = v0; gate[q][1] = v1;
                            }
                            int ci = ((hh * 2 + mt) * 2 + rh) * 4 + d * 2;
                            float hn[2];
#pragma unroll
                            for (int dd = 0; dd < 2; dd++) {
                                float c_ = sigf(gate[1][dd]) * creg[ci + dd]
                                         + sigf(gate[0][dd]) * tanhf(gate[2][dd]);
                                creg[ci + dd] = c_;
                                hn[dd] = sigf(gate[3][dd]) * tanhf(c_);
                            }
                            long base = ((long)s * B + b_row2) * H + j;
                            *(__half2*)&hout[base] = __floats2half2_rn(hn[0], hn[1]);
                        }
                    }
                }
            }
        }

        // attention for step it-1, group-local rows: sb = s*B + m0 + bx*32 + idx
        if (DEC && it >= 1) {
#pragma unroll 1
            for (int rep = 0; rep < 4; rep++) {
                int sb = s * B + m0 + bx * 32 + w + rep * 8;
                attn_one(hin, sb, lane, Wfcout, it - 1);
            }
        }

        if (it + 1 < NSTEP) group_bar(gctr, it);
    }

    if (!DEC) {
#pragma unroll
        for (int hh = 0; hh < 2; hh++)
#pragma unroll
            for (int mt = 0; mt < 2; mt++)
#pragma unroll
                for (int rh = 0; rh < 2; rh++)
#pragma unroll
                    for (int d = 0; d < 2; d++) {
                        int b_row2 = m0 + wm * 32 + mt * 16 + lq + rh * 8;
                        int j = bx * 64 + hh * 32 + (wn * 2 + d) * 8 + lr * 2;
                        int ci = ((hh * 2 + mt) * 2 + rh) * 4 + d * 2;
                        *(float2*)&g_c[((long)s * B + b_row2) * H + j] =
                            make_float2(creg[ci], creg[ci + 1]);
                    }
    }
}

// ---------------- per-(t,s,b) scalars ----------------
__global__ void pc_scal_kernel() {
    int gtid = blockIdx.x * blockDim.x + threadIdx.x;
    int warp = gtid >> 5;
    int lane = threadIdx.x & 31;
    if (warp >= T * S * B) return;
    int s = (warp >> 10) & 7;

    const __half2* ep = (const __half2*)(g_enc16 + (long)warp * H);
    const float* wb = g_wbqk + s * H;
    const float* wv = g_wvu + s * H;
    float db = 0.f, dv = 0.f;
#pragma unroll
    for (int u = 0; u < 2; u++) {
        int e = lane * 4 + u * 128;
        float2 e0 = __half22float2(ep[lane * 2 + u * 64]);
        float2 e1 = __half22float2(ep[lane * 2 + 1 + u * 64]);
        float4 b4 = *(const float4*)&wb[e];
        float4 v4 = *(const float4*)&wv[e];
        db += e0.x * b4.x + e0.y * b4.y + e1.x * b4.z + e1.y * b4.w;
        dv += e0.x * v4.x + e0.y * v4.y + e1.x * v4.z + e1.y * v4.w;
    }
#pragma unroll
    for (int off = 16; off; off >>= 1) {
        db += __shfl_xor_sync(0xffffffffu, db, off);
        dv += __shfl_xor_sync(0xffffffffu, dv, off);
    }
    if (lane == 0) {
        g_bqk[warp] = db + g_cbqk[s];
        g_vu[warp]  = dv + g_cvu[s];
    }
}

// ---------------- final 8->1 mix ----------------
__global__ void final_kernel(const float* __restrict__ Wfc, const float* __restrict__ bfc,
                             float* __restrict__ out) {
    int i = blockIdx.x * blockDim.x + threadIdx.x;
    if (i >= B * L) return;
    int b = i / L, l = i % L;
    float acc = bfc[0];
#pragma unroll
    for (int s = 0; s < S; s++)
        acc += g_outs[(long)l * S * B + (long)s * B + b] * Wfc[s];
    out[i] = acc;
}

// ---------------- host launch ----------------
extern "C" void kernel_launch(void* const* d_in, const int* in_sizes, int n_in,
                              void* d_out, int out_size) {
    const float* x       = (const float*)d_in[0];
    const float* tgt     = (const float*)d_in[1];
    const float* W_ih_e  = (const float*)d_in[2];
    const float* W_hh_e  = (const float*)d_in[3];
    const float* b_ih_e  = (const float*)d_in[4];
    const float* b_hh_e  = (const float*)d_in[5];
    const float* W_ih_d  = (const float*)d_in[6];
    const float* W_hh_d  = (const float*)d_in[7];
    const float* b_ih_d  = (const float*)d_in[8];
    const float* b_hh_d  = (const float*)d_in[9];
    const float* W_in    = (const float*)d_in[10];
    const float* b_in    = (const float*)d_in[11];
    const float* W_out   = (const float*)d_in[12];
    const float* b_out   = (const float*)d_in[13];
    const float* W_fcout = (const float*)d_in[14];
    const float* b_fcout = (const float*)d_in[15];
    const float* W_fc    = (const float*)d_in[16];
    const float* b_fc    = (const float*)d_in[17];
    float* out = (float*)d_out;

    __half *gin16, *x16, *w16ih, *enc16, *k2h, *hA, *hB, *W16e, *W16d, *M1h;
    float *k2b, *b12;
    cudaGetSymbolAddress((void**)&gin16, g_Gin16);
    cudaGetSymbolAddress((void**)&x16,   g_x16);
    cudaGetSymbolAddress((void**)&w16ih, g_W16ih);
    cudaGetSymbolAddress((void**)&enc16, g_enc16);
    cudaGetSymbolAddress((void**)&k2h,   g_k2h);
    cudaGetSymbolAddress((void**)&hA,    g_h16A);
    cudaGetSymbolAddress((void**)&hB,    g_h16B);
    cudaGetSymbolAddress((void**)&W16e,  g_W16e);
    cudaGetSymbolAddress((void**)&W16d,  g_W16d);
    cudaGetSymbolAddress((void**)&M1h,   g_M1h);
    cudaGetSymbolAddress((void**)&k2b,   g_k2b);
    cudaGetSymbolAddress((void**)&b12,   g_b12d);

    static int smem_set = 0;
    if (!smem_set) {
        cudaFuncSetAttribute(step16_p<0>, cudaFuncAttributeMaxDynamicSharedMemorySize, STEP_SMEM);
        cudaFuncSetAttribute(step16_p<1>, cudaFuncAttributeMaxDynamicSharedMemorySize, STEP_SMEM);
        smem_set = 1;
    }

    prep_fused<<<(int)(((long)B * 96 * (KX / 8) + 255) / 256), 256>>>(x, tgt, b_ih_d, b_hh_d);
    conv_wih<<<(int)(((long)S * G * (KX / 8) + 255) / 256), 256>>>(W_ih_e);
    conv_w16_both<<<(int)(2 * ((long)S * G * H) / 256), 256>>>(W_hh_e, W_hh_d);
    pc_a<<<S * H * 32 / 256, 256>>>(W_out, W_fcout, W_in, b_in);
    pc_b<<<S * H * 32 / 256, 256>>>(W_in);
    pc_c<<<1, 256>>>(b_in, W_fcout, b_fcout, b_out);
    pc_m1<<<dim3(16, 16, 8), dim3(16, 16)>>>(W_in);

    gemm_f16<<<dim3(G / 128, B / 128, 96), 256>>>(
        x16, (long)KX, 96 * KX,
        w16ih, (long)G * KX, KX,
        b_ih_e, b_hh_e, G,
        gin16, (long)B * G, G, KX / 32, 12);

    step16_p<0><<<NBP, 256, STEP_SMEM>>>(
        hA, nullptr, nullptr, W16e,
        nullptr, nullptr, gin16, enc16, nullptr);

    pc_scal_kernel<<<(T * S * B * 32 + 255) / 256, 256>>>();
    gemm_f16<<<dim3(H / 128, B / 128, T * S), 256>>>(
        enc16, (long)B * H, H,
        M1h, (long)H * H, H,
        k2b, nullptr, H,
        k2h, (long)B * H, H, H / 32, 1);

    step16_p<1><<<NBP, 256, STEP_SMEM>>>(
        enc16 + (long)11 * SBH, hA, hB, W16d,
        b12, W_ih_d, nullptr, nullptr, W_fcout);

    final_kernel<<<(B * L + 255) / 256, 256>>>(W_fc, b_fc, out);
}